// round 1
// baseline (speedup 1.0000x reference)
#include <cuda_runtime.h>

// Invert4_10: 16-step spiking scan, elementwise over x (8,4096,4096) fp32.
// Key simplifications:
//   spike((v-T)/(|v|+1)) == (v > T)   (denominator strictly positive)
//   z in {0,1}  ->  two FFMA-imm + one compare per step
//   step 0: a = |x| >= 0 > T0=-0.2537  ->  z0 = 1 always (peeled)

static __device__ __forceinline__ float eval_abs(float a) {
    // Baked constants (identical decimal -> identical fp32 rounding as numpy).
    const float Hc[16] = {-0.00181154f, 0.8721661f, 0.9177631f, 0.9392744f,
                          0.5681609f, 0.9465831f, 0.6847087f, 0.45589155f,
                          0.57916474f, 0.7803396f, 0.28270212f, 0.49239117f,
                          1.1224731f, 0.5738949f, 0.32048506f, 0.2620882f};
    const float Dc[16] = {0.0931013f, 0.09543603f, -0.00957536f, -0.02775419f,
                          0.07635077f, -0.02604962f, -0.01608226f, -0.0154707f,
                          -0.01741009f, -0.00761568f, -0.00868225f, -0.01600825f,
                          -0.00795393f, -0.0046836f, -0.00339996f, -0.00177163f};
    const float Tc[16] = {-0.25367174f, -0.35691947f, 0.35702407f, 1.8097845f,
                          -0.8933508f, 0.74517566f, 0.57702994f, 0.56928945f,
                          0.61470956f, 0.43903926f, 0.20668195f, 0.6593264f,
                          0.35631987f, 0.15981139f, -0.12464668f, -0.22194518f};

    // Peeled step 0: z=1 guaranteed (a >= 0 > T[0]).
    float v = a;
    float z = 1.0f;
    float out = Dc[0];

#pragma unroll
    for (int t = 1; t < 16; ++t) {
        v = fmaf(z, -Hc[t], v);            // v -= z*h  (FFMA with imm multiplier)
        z = (v > Tc[t]) ? 1.0f : 0.0f;     // spike == sign test, no divide
        out = fmaf(z, Dc[t], out);         // out += z*d
    }
    return out;
}

static __device__ __forceinline__ float run1(float x) {
    float a = fabsf(x);
    float out = eval_abs(a);
    float r = copysignf(out, x);
    // jnp.sign(0) == 0 -> output must be 0 at x == 0 (also handles -0.0).
    return (x == 0.0f) ? 0.0f : r;
}

static __device__ __forceinline__ float4 run4(float4 p) {
    float4 r;
    r.x = run1(p.x);
    r.y = run1(p.y);
    r.z = run1(p.z);
    r.w = run1(p.w);
    return r;
}

__global__ void __launch_bounds__(256)
invert_kernel(const float4* __restrict__ x, float4* __restrict__ y, int nvec) {
    const int stride = blockDim.x * gridDim.x;
    const int i = blockIdx.x * blockDim.x + threadIdx.x;
    const int i0 = i;
    const int i1 = i + stride;
    const int i2 = i + 2 * stride;
    const int i3 = i + 3 * stride;

    // Front-batched streaming loads (MLP=4), .cs policy: data touched once.
    float4 a0, a1, a2, a3;
    const bool m0 = (i0 < nvec), m1 = (i1 < nvec), m2 = (i2 < nvec), m3 = (i3 < nvec);
    if (m0) a0 = __ldcs(x + i0);
    if (m1) a1 = __ldcs(x + i1);
    if (m2) a2 = __ldcs(x + i2);
    if (m3) a3 = __ldcs(x + i3);

    if (m0) __stcs(y + i0, run4(a0));
    if (m1) __stcs(y + i1, run4(a1));
    if (m2) __stcs(y + i2, run4(a2));
    if (m3) __stcs(y + i3, run4(a3));
}

__global__ void invert_tail_kernel(const float* __restrict__ x, float* __restrict__ y,
                                   int start, int n) {
    int i = start + blockIdx.x * blockDim.x + threadIdx.x;
    if (i < n) y[i] = run1(x[i]);
}

extern "C" void kernel_launch(void* const* d_in, const int* in_sizes, int n_in,
                              void* d_out, int out_size) {
    const float* x = (const float*)d_in[0];
    float* y = (float*)d_out;
    const long long n = (long long)in_sizes[0];

    const long long nvec = n >> 2;          // float4 count
    const int threads = 256;
    const int vpt = 4;                      // float4 per thread
    long long blocks = (nvec + (long long)threads * vpt - 1) / ((long long)threads * vpt);
    if (blocks < 1) blocks = 1;
    invert_kernel<<<(unsigned)blocks, threads>>>((const float4*)x, (float4*)y, (int)nvec);

    const int rem = (int)(n & 3LL);
    if (rem) {
        invert_tail_kernel<<<1, 32>>>(x, y, (int)(n - rem), (int)n);
    }
}

// round 2
// speedup vs baseline: 1.1173x; 1.1173x over previous
#include <cuda_runtime.h>

// Invert4_10: 16-step spiking scan, elementwise.
//   spike((v-T)/(|v|+1)) == (v > T)     (denominator strictly positive)
//   z in {0,1}  ->  predicate the state updates instead of materializing z:
//       p = (v > T_t);  @p out += d_t;  @p v -= h_{t+1}
//   Step 0 peeled: z0 = (|x| > T0 = -0.2537) = 1 always.
// Constants are PTX decimal immediates (fold into FADD/FSETP imm encodings,
// no constant registers -> register pressure stays low).

#define STEP(Tt, Dt, nHn)                              \
  asm("{\n\t.reg .pred p;\n\t"                         \
      "setp.gt.f32 p, %0, " #Tt ";\n\t"                \
      "@p add.f32 %1, %1, " #Dt ";\n\t"                \
      "@p add.f32 %0, %0, " #nHn ";\n\t}"              \
      : "+f"(v), "+f"(out))

#define LAST(Tt, Dt)                                   \
  asm("{\n\t.reg .pred p;\n\t"                         \
      "setp.gt.f32 p, %0, " #Tt ";\n\t"                \
      "@p add.f32 %1, %1, " #Dt ";\n\t}"               \
      : "+f"(v), "+f"(out))

static __device__ __forceinline__ float run1(float x) {
    float a = fabsf(x);                 // folds into |src| of the init FADD
    float v = a - 0.8721661f;           // z0 = 1: v = a - h1
    float out = 0.0931013f;             // out = d0

    // STEP(T_t, d_t, -h_{t+1}) for t = 1..14, then LAST(T15, d15)
    STEP(-0.35691947,  0.09543603, -0.9177631);
    STEP( 0.35702407, -0.00957536, -0.9392744);
    STEP( 1.8097845,  -0.02775419, -0.5681609);
    STEP(-0.8933508,   0.07635077, -0.9465831);
    STEP( 0.74517566, -0.02604962, -0.6847087);
    STEP( 0.57702994, -0.01608226, -0.45589155);
    STEP( 0.56928945, -0.0154707,  -0.57916474);
    STEP( 0.61470956, -0.01741009, -0.7803396);
    STEP( 0.43903926, -0.00761568, -0.28270212);
    STEP( 0.20668195, -0.00868225, -0.49239117);
    STEP( 0.6593264,  -0.01600825, -1.1224731);
    STEP( 0.35631987, -0.00795393, -0.5738949);
    STEP( 0.15981139, -0.0046836,  -0.32048506);
    STEP(-0.12464668, -0.00339996, -0.2620882);
    LAST(-0.22194518, -0.00177163);

    float r = copysignf(out, x);        // single LOP3
    return (x == 0.0f) ? 0.0f : r;      // jnp.sign(0) == 0  (exact zeros occur)
}

static __device__ __forceinline__ float4 run4(float4 p) {
    float4 r;
    r.x = run1(p.x);
    r.y = run1(p.y);
    r.z = run1(p.z);
    r.w = run1(p.w);
    return r;
}

// Exact-cover variant: grid covers nvec exactly, no bounds checks.
__global__ void __launch_bounds__(256)
invert_kernel_exact(const float4* __restrict__ x, float4* __restrict__ y) {
    const int stride = blockDim.x * gridDim.x;
    const int i = blockIdx.x * blockDim.x + threadIdx.x;

    // Front-batched streaming loads (MLP=4); data touched once -> .cs
    float4 a0 = __ldcs(x + i);
    float4 a1 = __ldcs(x + i + stride);
    float4 a2 = __ldcs(x + i + 2 * stride);
    float4 a3 = __ldcs(x + i + 3 * stride);

    __stcs(y + i,              run4(a0));
    __stcs(y + i + stride,     run4(a1));
    __stcs(y + i + 2 * stride, run4(a2));
    __stcs(y + i + 3 * stride, run4(a3));
}

// Guarded fallback for non-divisible sizes.
__global__ void __launch_bounds__(256)
invert_kernel_guard(const float4* __restrict__ x, float4* __restrict__ y, int nvec) {
    const int stride = blockDim.x * gridDim.x;
    const int i = blockIdx.x * blockDim.x + threadIdx.x;
    const int i0 = i, i1 = i + stride, i2 = i + 2 * stride, i3 = i + 3 * stride;

    float4 a0, a1, a2, a3;
    const bool m0 = (i0 < nvec), m1 = (i1 < nvec), m2 = (i2 < nvec), m3 = (i3 < nvec);
    if (m0) a0 = __ldcs(x + i0);
    if (m1) a1 = __ldcs(x + i1);
    if (m2) a2 = __ldcs(x + i2);
    if (m3) a3 = __ldcs(x + i3);

    if (m0) __stcs(y + i0, run4(a0));
    if (m1) __stcs(y + i1, run4(a1));
    if (m2) __stcs(y + i2, run4(a2));
    if (m3) __stcs(y + i3, run4(a3));
}

__global__ void invert_tail_kernel(const float* __restrict__ x, float* __restrict__ y,
                                   int start, int n) {
    int i = start + blockIdx.x * blockDim.x + threadIdx.x;
    if (i < n) y[i] = run1(x[i]);
}

extern "C" void kernel_launch(void* const* d_in, const int* in_sizes, int n_in,
                              void* d_out, int out_size) {
    const float* x = (const float*)d_in[0];
    float* y = (float*)d_out;
    const long long n = (long long)in_sizes[0];

    const long long nvec = n >> 2;        // float4 count
    const int threads = 256;
    const int vpt = 4;                    // float4 per thread
    const long long per_blk = (long long)threads * vpt;

    if (nvec > 0 && (nvec % per_blk) == 0) {
        invert_kernel_exact<<<(unsigned)(nvec / per_blk), threads>>>(
            (const float4*)x, (float4*)y);
    } else if (nvec > 0) {
        long long blocks = (nvec + per_blk - 1) / per_blk;
        invert_kernel_guard<<<(unsigned)blocks, threads>>>(
            (const float4*)x, (float4*)y, (int)nvec);
    }

    const int rem = (int)(n & 3LL);
    if (rem) {
        invert_tail_kernel<<<1, 32>>>(x, y, (int)(n - rem), (int)n);
    }
}